// round 14
// baseline (speedup 1.0000x reference)
#include <cuda_runtime.h>
#include <cuda_bf16.h>
#include <cstdint>
#include <cfloat>

#define LEVELS 2
#define BATCH  16
#define DIM    256
#define TLEN   2048
#define NPTS   (BATCH * TLEN)       // 32768 points per level
#define KCODES 1024
#define NELEM  (BATCH * DIM * TLEN) // 8388608 per level
#define GATHER_BLOCKS (BATCH * (TLEN / 32))
#define TAU_S  0.25f                // 10x sigma of dropped x.e_lo term (sigma~0.025)
#define NTILES (LEVELS * (NPTS / 64))   // 1024 work items

// ---------------- scratch (no allocations allowed) ----------------
__device__ float    g_bt[(size_t)LEVELS * DIM * KCODES];   // codebook transposed (refine)
__device__ float2   g_cninit[LEVELS * (KCODES / 2)];       // packed (-cn/2) pairs
__device__ float    g_partial[LEVELS][GATHER_BLOCKS];
__device__ int      g_idx[LEVELS][NPTS];
__device__ int      g_refine_count[LEVELS];
__device__ int      g_refine_list[LEVELS][NPTS];
__device__ int      g_tile_ctr;
// bf16 splits packed as u32 pairs (elem 2d in low half): [p][d] and [c][d]
__device__ unsigned g_xhi[(size_t)LEVELS * NPTS * (DIM / 2)];
__device__ unsigned g_xlo[(size_t)LEVELS * NPTS * (DIM / 2)];
__device__ unsigned g_ehi[(size_t)LEVELS * KCODES * (DIM / 2)];

// ---------------- helpers ----------------
__device__ __forceinline__ void cp16(void* dst, const void* src) {
    unsigned s = (unsigned)__cvta_generic_to_shared(dst);
    asm volatile("cp.async.cg.shared.global [%0], [%1], 16;" :: "r"(s), "l"(src) : "memory");
}
#define CP_COMMIT() asm volatile("cp.async.commit_group;" ::: "memory")
#define CP_WAIT2()  asm volatile("cp.async.wait_group 2;" ::: "memory")
#define CP_WAIT0()  asm volatile("cp.async.wait_group 0;" ::: "memory")

__device__ __forceinline__ void lda4(uint32_t r[4], uint32_t addr) {
    asm volatile("ldmatrix.sync.aligned.m8n8.x4.shared.b16 {%0,%1,%2,%3}, [%4];"
                 : "=r"(r[0]), "=r"(r[1]), "=r"(r[2]), "=r"(r[3]) : "r"(addr));
}
__device__ __forceinline__ void mma16816(float d[4], const uint32_t a[4], const uint32_t b[2]) {
    asm volatile("mma.sync.aligned.m16n8k16.row.col.f32.bf16.bf16.f32 "
                 "{%0,%1,%2,%3}, {%4,%5,%6,%7}, {%8,%9}, {%0,%1,%2,%3};"
                 : "+f"(d[0]), "+f"(d[1]), "+f"(d[2]), "+f"(d[3])
                 : "r"(a[0]), "r"(a[1]), "r"(a[2]), "r"(a[3]), "r"(b[0]), "r"(b[1]));
}

// ---------------- kernel: split+transpose h -> x_hi/x_lo bf16 [lvl][p][d] ----------------
__global__ __launch_bounds__(256)
void xsplit_kernel(const float* __restrict__ h_top, const float* __restrict__ h_bot) {
    __shared__ float s[32][65];
    int z = blockIdx.z, lvl = z >> 4, b = z & 15;
    const float* h = lvl ? h_bot : h_top;
    int t0 = blockIdx.x * 32, d0 = blockIdx.y * 64;
    int tid = threadIdx.x, lane = tid & 31, w = tid >> 5;
#pragma unroll
    for (int k = 0; k < 8; k++) {
        int dl = w + 8 * k;
        s[lane][dl] = h[((size_t)b * DIM + d0 + dl) * TLEN + t0 + lane];
    }
    __syncthreads();
    int pl = tid >> 3, q = tid & 7;
    int p = b * TLEN + t0 + pl;
    size_t rowbase = ((size_t)lvl * NPTS + p) * (DIM / 2) + (d0 >> 1);
#pragma unroll
    for (int k = 0; k < 4; k++) {
        int d2 = q + 8 * k;
        float v0 = s[pl][2 * d2], v1 = s[pl][2 * d2 + 1];
        __nv_bfloat16 h0 = __float2bfloat16(v0), h1 = __float2bfloat16(v1);
        __nv_bfloat16 l0 = __float2bfloat16(v0 - __bfloat162float(h0));
        __nv_bfloat16 l1 = __float2bfloat16(v1 - __bfloat162float(h1));
        g_xhi[rowbase + d2] = ((unsigned)__bfloat16_as_ushort(h1) << 16) | __bfloat16_as_ushort(h0);
        g_xlo[rowbase + d2] = ((unsigned)__bfloat16_as_ushort(l1) << 16) | __bfloat16_as_ushort(l0);
    }
}

// ---------------- kernel: codebook split (hi only) + (-cn/2) + counter resets ----------------
__global__ __launch_bounds__(256)
void ecnorm_kernel(const float* __restrict__ cb_top, const float* __restrict__ cb_bot) {
    __shared__ float s8[8];
    int lvl = blockIdx.y;
    if (blockIdx.x == 0 && threadIdx.x == 0) {
        g_refine_count[lvl] = 0;
        if (lvl == 0) g_tile_ctr = 0;
    }
    const float* cb = lvl ? cb_bot : cb_top;
    int w = threadIdx.x >> 5, lane = threadIdx.x & 31;
    int c = blockIdx.x * 8 + w;
    const float* row = cb + (size_t)c * DIM;
    size_t rowbase = ((size_t)lvl * KCODES + c) * (DIM / 2);
    float sacc = 0.f;
#pragma unroll
    for (int k = 0; k < 4; k++) {
        int d2 = lane + 32 * k;
        float v0 = row[2 * d2], v1 = row[2 * d2 + 1];
        sacc = fmaf(v0, v0, sacc);
        sacc = fmaf(v1, v1, sacc);
        __nv_bfloat16 h0 = __float2bfloat16(v0), h1 = __float2bfloat16(v1);
        g_ehi[rowbase + d2] = ((unsigned)__bfloat16_as_ushort(h1) << 16) | __bfloat16_as_ushort(h0);
    }
#pragma unroll
    for (int o = 16; o; o >>= 1) sacc += __shfl_down_sync(0xffffffffu, sacc, o);
    if (lane == 0) s8[w] = sacc;
    __syncthreads();
    if (threadIdx.x < 4)
        g_cninit[lvl * (KCODES / 2) + blockIdx.x * 4 + threadIdx.x] =
            make_float2(-0.5f * s8[2 * threadIdx.x], -0.5f * s8[2 * threadIdx.x + 1]);
}

// ---------------- kernel: transpose codebook to [d][c] (refine uses it) ----------------
__global__ __launch_bounds__(256)
void btrans_kernel(const float* __restrict__ cb_top, const float* __restrict__ cb_bot) {
    __shared__ float s[32][33];
    int lvl = blockIdx.z;
    const float* cb = lvl ? cb_bot : cb_top;
    int c0 = blockIdx.x * 32, d0 = blockIdx.y * 32;
    int lx = threadIdx.x & 31, ly = threadIdx.x >> 5;
#pragma unroll
    for (int k = 0; k < 4; k++)
        s[ly + 8 * k][lx] = cb[(size_t)(c0 + ly + 8 * k) * DIM + d0 + lx];
    __syncthreads();
#pragma unroll
    for (int k = 0; k < 4; k++)
        g_bt[((size_t)lvl * DIM + d0 + ly + 8 * k) * KCODES + c0 + lx] = s[lx][ly + 8 * k];
}

// ---------------- argmin GEMM: x.e_hi on tensor pipe (2 GEMMs), persistent CTAs ----------------
// smem: A_hi 32KB | A_lo 32KB | B ring 4 x 4KB (e_hi only, 32B rows, XOR swizzle) => 80KB/CTA
#define SM_AHI 0
#define SM_ALO 32768
#define SM_B   65536
#define SM_RED 65536             // reduce scratch reuses B ring after mainloop
#define ARG_SMEM (65536 + 4 * 4096)

// B slot layout: row r (code), seg s (16B) at r*32 + ((s ^ ((r>>2)&1))<<4)
// -> any 8 consecutive rows at one seg hit 8 distinct 16B groups mod 128B (conflict-free).
__device__ __forceinline__ void issueB(char* smem, int s, int tid, size_t L) {
    int nt = s >> 4, ch = s & 15, buf = s & 3;
    int row = tid >> 1, sg = tid & 1;
    char* bb = smem + SM_B + buf * 4096;
    size_t src = (L + nt * 128 + row) * (size_t)128 + ch * 8 + sg * 4;
    cp16(bb + row * 32 + ((sg ^ ((row >> 2) & 1)) << 4), &g_ehi[src]);
    CP_COMMIT();
}

__global__ __launch_bounds__(256, 2)
void argmin_kernel() {
    extern __shared__ __align__(128) char smem[];
    __shared__ int s_pos;
    int tid = threadIdx.x, lane = tid & 31, wid = tid >> 5;
    int wm = wid >> 2, wn = wid & 3;           // 2 warp-rows (32M) x 4 warp-cols (32N)
    uint32_t sb = (uint32_t)__cvta_generic_to_shared(smem);

    for (;;) {
        if (tid == 0) s_pos = atomicAdd(&g_tile_ctr, 1);
        __syncthreads();                        // s_pos visible; prev tile smem use done
        int pos = s_pos;
        if (pos >= NTILES) break;
        int lvl = pos >> 9;
        int m0 = (pos & 511) * 64;
        size_t XL = (size_t)lvl * NPTS;
        size_t EL = (size_t)lvl * KCODES;

        // ---- prologue: A (hi+lo, 64 rows) resident swizzled smem; then B chunks 0..2 ----
#pragma unroll
        for (int i = 0; i < 8; i++) {
            int idx = tid + i * 256;            // 2048 segs per part
            int row = idx >> 5, seg = idx & 31;
            int soff = ((seg ^ (row & 7)) << 4);
            size_t src = (XL + m0 + row) * (size_t)128 + seg * 4;
            cp16(smem + SM_AHI + row * 512 + soff, &g_xhi[src]);
            cp16(smem + SM_ALO + row * 512 + soff, &g_xlo[src]);
        }
        CP_COMMIT();
        issueB(smem, 0, tid, EL);
        issueB(smem, 1, tid, EL);
        issueB(smem, 2, tid, EL);

        float tb[4], t2[4];
        int   ti[4];
#pragma unroll
        for (int r = 0; r < 4; r++) { tb[r] = -FLT_MAX; t2[r] = -FLT_MAX; ti[r] = 0; }

#pragma unroll 1
        for (int nt = 0; nt < 8; nt++) {
            // init accumulators with -cn/2 (per-column)
            float acc[2][4][4];
#pragma unroll
            for (int j = 0; j < 4; j++) {
                int c0 = nt * 128 + wn * 32 + j * 8 + (lane & 3) * 2;
                float2 ci = g_cninit[lvl * (KCODES / 2) + (c0 >> 1)];
#pragma unroll
                for (int mi = 0; mi < 2; mi++) {
                    acc[mi][j][0] = ci.x; acc[mi][j][1] = ci.y;
                    acc[mi][j][2] = ci.x; acc[mi][j][3] = ci.y;
                }
            }

#pragma unroll 1
            for (int ch = 0; ch < 16; ch++) {
                int s = nt * 16 + ch;
                if (s < 125) CP_WAIT2();      // groups s+1, s+2 pending; s complete
                else         CP_WAIT0();      // tail: drain (last 3 chunks)
                __syncthreads();
                if (s < 125) issueB(smem, s + 3, tid, EL);   // slot (s-1)&3, safe post-sync
                uint32_t bb = sb + SM_B + (s & 3) * 4096;

                // A fragments: 2 m-tiles (16 rows each), hi + lo
                uint32_t ah[2][4], al[2][4];
#pragma unroll
                for (int mi = 0; mi < 2; mi++) {
                    int p = wm * 32 + mi * 16 + (lane & 7) + ((lane >> 3) & 1) * 8;
                    int seg = ch * 2 + (lane >> 4);
                    uint32_t off = p * 512 + ((seg ^ (p & 7)) << 4);
                    lda4(ah[mi], sb + SM_AHI + off);
                    lda4(al[mi], sb + SM_ALO + off);
                }

                // B fragments (e_hi only) via x4: matrix g = (n-tile g>>1, k-seg g&1)
                uint32_t bh[8];
                {
                    int g = lane >> 3, i = lane & 7;
                    int row0 = wn * 32 + (g >> 1) * 8 + i;     // n-tiles 0,1
                    int row1 = row0 + 16;                      // n-tiles 2,3
                    uint32_t a0 = bb + row0 * 32 + (((g & 1) ^ ((row0 >> 2) & 1)) << 4);
                    uint32_t a1 = bb + row1 * 32 + (((g & 1) ^ ((row1 >> 2) & 1)) << 4);
                    lda4(&bh[0], a0);
                    lda4(&bh[4], a1);
                }
#pragma unroll
                for (int j = 0; j < 4; j++) {
#pragma unroll
                    for (int mi = 0; mi < 2; mi++) {
                        mma16816(acc[mi][j], ah[mi], &bh[2 * j]);
                        mma16816(acc[mi][j], al[mi], &bh[2 * j]);
                    }
                }
            }

            // fold N-tile into running per-row top-2 (ascending c -> first-min tiebreak)
#pragma unroll
            for (int j = 0; j < 4; j++) {
                int cbase = nt * 128 + wn * 32 + j * 8 + (lane & 3) * 2;
#pragma unroll
                for (int mi = 0; mi < 2; mi++)
#pragma unroll
                    for (int rh = 0; rh < 2; rh++) {
                        int r = mi * 2 + rh;
#pragma unroll
                        for (int cc = 0; cc < 2; cc++) {
                            float v = acc[mi][j][rh * 2 + cc];
                            int c = cbase + cc;
                            if (v > tb[r]) { t2[r] = tb[r]; tb[r] = v; ti[r] = c; }
                            else if (v > t2[r]) t2[r] = v;
                        }
                    }
            }
        }

        // quad merge (4 lanes share each row)
#pragma unroll
        for (int k = 1; k <= 2; k <<= 1) {
#pragma unroll
            for (int r = 0; r < 4; r++) {
                float ob = __shfl_xor_sync(0xffffffffu, tb[r], k);
                float o2 = __shfl_xor_sync(0xffffffffu, t2[r], k);
                int   oi = __shfl_xor_sync(0xffffffffu, ti[r], k);
                if (ob > tb[r] || (ob == tb[r] && oi < ti[r])) {
                    t2[r] = fmaxf(tb[r], o2); tb[r] = ob; ti[r] = oi;
                } else {
                    t2[r] = fmaxf(t2[r], ob);
                }
            }
        }

        __syncthreads();                         // B ring drained; reuse as reduce scratch
        float* rv  = (float*)(smem + SM_RED);    // 64 rows x 4 wn
        float* r2v = rv + 256;
        int*   rix = (int*)(r2v + 256);
        if ((lane & 3) == 0) {
#pragma unroll
            for (int r = 0; r < 4; r++) {
                int row = wm * 32 + (r >> 1) * 16 + (r & 1) * 8 + (lane >> 2);
                rv[row * 4 + wn]  = tb[r];
                r2v[row * 4 + wn] = t2[r];
                rix[row * 4 + wn] = ti[r];
            }
        }
        __syncthreads();
        if (tid < 64) {
            float bv = rv[tid * 4];
            float bs = r2v[tid * 4];
            int   bi = rix[tid * 4];
#pragma unroll
            for (int x = 1; x < 4; x++) {
                float v  = rv[tid * 4 + x];
                float v2 = r2v[tid * 4 + x];
                int   ii = rix[tid * 4 + x];
                if (v > bv || (v == bv && ii < bi)) { bs = fmaxf(bv, v2); bv = v; bi = ii; }
                else                                 bs = fmaxf(bs, v);
            }
            g_idx[lvl][m0 + tid] = bi;
            if (bv - bs < TAU_S) {
                int p2 = atomicAdd(&g_refine_count[lvl], 1);
                g_refine_list[lvl][p2] = m0 + tid;
            }
        }
    }
}

// ---------------- kernel: double-f32 exact refinement (1 point/block, 1 code/thread) ----------------
__global__ __launch_bounds__(1024)
void refine_kernel(const float* __restrict__ h_top, const float* __restrict__ h_bot) {
    int lvl = blockIdx.y;
    const float* h = lvl ? h_bot : h_top;
    const float* bt = g_bt + (size_t)lvl * DIM * KCODES;
    int cnt = g_refine_count[lvl];

    __shared__ float xs[DIM];
    __shared__ float rh[1024], rl[1024];
    __shared__ int   rix[1024];

    int tid = threadIdx.x;
    int c = tid;

    for (int e = blockIdx.x; e < cnt; e += gridDim.x) {
        int p = g_refine_list[lvl][e];
        int b = p / TLEN, t = p % TLEN;
        __syncthreads();
        if (tid < DIM)
            xs[tid] = h[((size_t)b * DIM + tid) * TLEN + t];
        __syncthreads();

        float hi = 0.f, lo = 0.f;
#pragma unroll 8
        for (int d = 0; d < DIM; d++) {
            float ev = bt[(size_t)d * KCODES + c];
            float x  = xs[d];
            float s  = x - ev;
            float bb = s - x;
            float err = (x - (s - bb)) + ((-ev) - bb);
            float pq = s * s;
            float pe = fmaf(s, s, -pq);
            float cross = fmaf(2.f * s, err, fmaf(err, err, pe));
            float t1  = hi + pq;
            float bb2 = t1 - hi;
            float e2  = (hi - (t1 - bb2)) + (pq - bb2);
            hi = t1;
            lo += e2 + cross;
        }
        float th = hi + lo;
        float tl = lo - (th - hi);

        rh[tid] = th; rl[tid] = tl; rix[tid] = c;
        __syncthreads();
#pragma unroll
        for (int s = 512; s; s >>= 1) {
            if (tid < s) {
                float oh = rh[tid + s], ol = rl[tid + s];
                int   oi = rix[tid + s];
                float mh = rh[tid], ml = rl[tid];
                int   mi = rix[tid];
                if (oh < mh || (oh == mh && (ol < ml || (ol == ml && oi < mi)))) {
                    rh[tid] = oh; rl[tid] = ol; rix[tid] = oi;
                }
            }
            __syncthreads();
        }
        if (tid == 0) g_idx[lvl][p] = rix[0];
    }
}

// ---------------- kernel: gather z_q + per-block loss partials ----------------
__global__ __launch_bounds__(256)
void gather_kernel(const float* __restrict__ h_top, const float* __restrict__ h_bot,
                   const float* __restrict__ cb_top, const float* __restrict__ cb_bot,
                   float* __restrict__ out) {
    int lvl = blockIdx.z;
    const float* h  = lvl ? h_bot  : h_top;
    const float* cb = lvl ? cb_bot : cb_top;
    float* z = out + (size_t)lvl * NELEM;

    int b = blockIdx.y;
    int t0 = blockIdx.x * 32;
    int tid = threadIdx.x;

    __shared__ int   sidx[32];
    __shared__ float sh[32 * 33];
    __shared__ float red[256];

    if (tid < 32) sidx[tid] = g_idx[lvl][b * TLEN + t0 + tid];
    __syncthreads();

    float lacc = 0.f;
    int j2 = tid >> 3, l8 = tid & 7;

    for (int dc = 0; dc < DIM; dc += 32) {
        float4 v = *(const float4*)(cb + (size_t)sidx[j2] * DIM + dc + l8 * 4);
        sh[(l8 * 4 + 0) * 33 + j2] = v.x;
        sh[(l8 * 4 + 1) * 33 + j2] = v.y;
        sh[(l8 * 4 + 2) * 33 + j2] = v.z;
        sh[(l8 * 4 + 3) * 33 + j2] = v.w;
        __syncthreads();
#pragma unroll
        for (int it = 0; it < 4; it++) {
            int i = tid + it * 256;
            int dl = i >> 5, j = i & 31;
            size_t off = ((size_t)b * DIM + dc + dl) * TLEN + t0 + j;
            float zz = sh[dl * 33 + j];
            z[off] = zz;
            float e = h[off] - zz;
            lacc = fmaf(e, e, lacc);
        }
        __syncthreads();
    }

    red[tid] = lacc;
    __syncthreads();
#pragma unroll
    for (int s = 128; s; s >>= 1) {
        if (tid < s) red[tid] += red[tid + s];
        __syncthreads();
    }
    if (tid == 0) g_partial[lvl][blockIdx.y * (TLEN / 32) + blockIdx.x] = red[0];
}

// ---------------- kernel: finalize scalars ----------------
__global__ __launch_bounds__(1024)
void finalize_kernel(float* __restrict__ out) {
    __shared__ int   hist[KCODES];
    __shared__ float red[1024];
    int tid = threadIdx.x;

    float sums[2];
#pragma unroll
    for (int lvl = 0; lvl < 2; lvl++) {
        red[tid] = g_partial[lvl][tid];
        __syncthreads();
        for (int s = 512; s; s >>= 1) {
            if (tid < s) red[tid] += red[tid + s];
            __syncthreads();
        }
        sums[lvl] = red[0];
        __syncthreads();
    }
    float loss = sums[0] * (1.f / (float)NELEM) + sums[1] * (1.f / (float)NELEM);

    float ppl[2];
#pragma unroll
    for (int lvl = 0; lvl < 2; lvl++) {
        hist[tid] = 0;
        __syncthreads();
#pragma unroll
        for (int i = 0; i < NPTS / 1024; i++)
            atomicAdd(&hist[g_idx[lvl][i * 1024 + tid]], 1);
        __syncthreads();
        float p = (float)hist[tid] * (1.f / (float)NPTS);
        red[tid] = p * logf(p + 1e-10f);
        __syncthreads();
        for (int s = 512; s; s >>= 1) {
            if (tid < s) red[tid] += red[tid + s];
            __syncthreads();
        }
        ppl[lvl] = expf(-red[0]);
        __syncthreads();
    }

    if (tid == 0) {
        size_t base = (size_t)2 * NELEM;
        out[base + 0] = loss;
        out[base + 1] = loss;
        out[base + 2] = ppl[0];
        out[base + 3] = ppl[1];
    }
}

// ---------------- launcher ----------------
extern "C" void kernel_launch(void* const* d_in, const int* in_sizes, int n_in,
                              void* d_out, int out_size) {
    const float* h_top  = (const float*)d_in[0];
    const float* h_bot  = (const float*)d_in[1];
    const float* cb_top = (const float*)d_in[2];
    const float* cb_bot = (const float*)d_in[3];
    float* out = (float*)d_out;

    cudaFuncSetAttribute(argmin_kernel,
                         cudaFuncAttributeMaxDynamicSharedMemorySize, ARG_SMEM);

    xsplit_kernel<<<dim3(TLEN / 32, DIM / 64, BATCH * LEVELS), 256>>>(h_top, h_bot);
    ecnorm_kernel<<<dim3(KCODES / 8, LEVELS), 256>>>(cb_top, cb_bot);
    btrans_kernel<<<dim3(KCODES / 32, DIM / 32, LEVELS), 256>>>(cb_top, cb_bot);
    argmin_kernel<<<296, 256, ARG_SMEM>>>();
    refine_kernel<<<dim3(512, LEVELS), 1024>>>(h_top, h_bot);
    gather_kernel<<<dim3(TLEN / 32, BATCH, LEVELS), 256>>>(h_top, h_bot, cb_top, cb_bot, out);
    finalize_kernel<<<1, 1024>>>(out);
}

// round 15
// speedup vs baseline: 1.4508x; 1.4508x over previous
#include <cuda_runtime.h>
#include <cuda_bf16.h>
#include <cstdint>
#include <cfloat>

#define LEVELS 2
#define BATCH  16
#define DIM    256
#define TLEN   2048
#define NPTS   (BATCH * TLEN)       // 32768 points per level
#define KCODES 1024
#define NELEM  (BATCH * DIM * TLEN) // 8388608 per level
#define GATHER_BLOCKS (BATCH * (TLEN / 32))
#define TAU_S  0.25f                // 10x sigma of dropped x.e_lo term (sigma~0.025)
#define TAU_EXACT 0.03f             // 30x RMS of plain-f32 stage-A distance error
#define NTILES (LEVELS * (NPTS / 64))   // 1024 work items

// ---------------- scratch (no allocations allowed) ----------------
__device__ float    g_bt[(size_t)LEVELS * DIM * KCODES];   // codebook transposed (refine)
__device__ float2   g_cninit[LEVELS * (KCODES / 2)];       // packed (-cn/2) pairs
__device__ float    g_partial[LEVELS][GATHER_BLOCKS];
__device__ int      g_idx[LEVELS][NPTS];
__device__ int      g_refine_count[LEVELS];
__device__ int      g_refine_list[LEVELS][NPTS];
__device__ int      g_tile_ctr;
// bf16 splits packed as u32 pairs (elem 2d in low half): [p][d] and [c][d]
__device__ unsigned g_xhi[(size_t)LEVELS * NPTS * (DIM / 2)];
__device__ unsigned g_xlo[(size_t)LEVELS * NPTS * (DIM / 2)];
__device__ unsigned g_ehi[(size_t)LEVELS * KCODES * (DIM / 2)];

// ---------------- helpers ----------------
__device__ __forceinline__ void cp16(void* dst, const void* src) {
    unsigned s = (unsigned)__cvta_generic_to_shared(dst);
    asm volatile("cp.async.cg.shared.global [%0], [%1], 16;" :: "r"(s), "l"(src) : "memory");
}
#define CP_COMMIT() asm volatile("cp.async.commit_group;" ::: "memory")
#define CP_WAIT2()  asm volatile("cp.async.wait_group 2;" ::: "memory")
#define CP_WAIT0()  asm volatile("cp.async.wait_group 0;" ::: "memory")

__device__ __forceinline__ void lda4(uint32_t r[4], uint32_t addr) {
    asm volatile("ldmatrix.sync.aligned.m8n8.x4.shared.b16 {%0,%1,%2,%3}, [%4];"
                 : "=r"(r[0]), "=r"(r[1]), "=r"(r[2]), "=r"(r[3]) : "r"(addr));
}
__device__ __forceinline__ void mma16816(float d[4], const uint32_t a[4], const uint32_t b[2]) {
    asm volatile("mma.sync.aligned.m16n8k16.row.col.f32.bf16.bf16.f32 "
                 "{%0,%1,%2,%3}, {%4,%5,%6,%7}, {%8,%9}, {%0,%1,%2,%3};"
                 : "+f"(d[0]), "+f"(d[1]), "+f"(d[2]), "+f"(d[3])
                 : "r"(a[0]), "r"(a[1]), "r"(a[2]), "r"(a[3]), "r"(b[0]), "r"(b[1]));
}

// ---------------- kernel: split+transpose h -> x_hi/x_lo bf16 [lvl][p][d] ----------------
__global__ __launch_bounds__(256)
void xsplit_kernel(const float* __restrict__ h_top, const float* __restrict__ h_bot) {
    __shared__ float s[32][65];
    int z = blockIdx.z, lvl = z >> 4, b = z & 15;
    const float* h = lvl ? h_bot : h_top;
    int t0 = blockIdx.x * 32, d0 = blockIdx.y * 64;
    int tid = threadIdx.x, lane = tid & 31, w = tid >> 5;
#pragma unroll
    for (int k = 0; k < 8; k++) {
        int dl = w + 8 * k;
        s[lane][dl] = h[((size_t)b * DIM + d0 + dl) * TLEN + t0 + lane];
    }
    __syncthreads();
    int pl = tid >> 3, q = tid & 7;
    int p = b * TLEN + t0 + pl;
    size_t rowbase = ((size_t)lvl * NPTS + p) * (DIM / 2) + (d0 >> 1);
#pragma unroll
    for (int k = 0; k < 4; k++) {
        int d2 = q + 8 * k;
        float v0 = s[pl][2 * d2], v1 = s[pl][2 * d2 + 1];
        __nv_bfloat16 h0 = __float2bfloat16(v0), h1 = __float2bfloat16(v1);
        __nv_bfloat16 l0 = __float2bfloat16(v0 - __bfloat162float(h0));
        __nv_bfloat16 l1 = __float2bfloat16(v1 - __bfloat162float(h1));
        g_xhi[rowbase + d2] = ((unsigned)__bfloat16_as_ushort(h1) << 16) | __bfloat16_as_ushort(h0);
        g_xlo[rowbase + d2] = ((unsigned)__bfloat16_as_ushort(l1) << 16) | __bfloat16_as_ushort(l0);
    }
}

// ---------------- kernel: codebook split (hi only) + (-cn/2) + counter resets ----------------
__global__ __launch_bounds__(256)
void ecnorm_kernel(const float* __restrict__ cb_top, const float* __restrict__ cb_bot) {
    __shared__ float s8[8];
    int lvl = blockIdx.y;
    if (blockIdx.x == 0 && threadIdx.x == 0) {
        g_refine_count[lvl] = 0;
        if (lvl == 0) g_tile_ctr = 0;
    }
    const float* cb = lvl ? cb_bot : cb_top;
    int w = threadIdx.x >> 5, lane = threadIdx.x & 31;
    int c = blockIdx.x * 8 + w;
    const float* row = cb + (size_t)c * DIM;
    size_t rowbase = ((size_t)lvl * KCODES + c) * (DIM / 2);
    float sacc = 0.f;
#pragma unroll
    for (int k = 0; k < 4; k++) {
        int d2 = lane + 32 * k;
        float v0 = row[2 * d2], v1 = row[2 * d2 + 1];
        sacc = fmaf(v0, v0, sacc);
        sacc = fmaf(v1, v1, sacc);
        __nv_bfloat16 h0 = __float2bfloat16(v0), h1 = __float2bfloat16(v1);
        g_ehi[rowbase + d2] = ((unsigned)__bfloat16_as_ushort(h1) << 16) | __bfloat16_as_ushort(h0);
    }
#pragma unroll
    for (int o = 16; o; o >>= 1) sacc += __shfl_down_sync(0xffffffffu, sacc, o);
    if (lane == 0) s8[w] = sacc;
    __syncthreads();
    if (threadIdx.x < 4)
        g_cninit[lvl * (KCODES / 2) + blockIdx.x * 4 + threadIdx.x] =
            make_float2(-0.5f * s8[2 * threadIdx.x], -0.5f * s8[2 * threadIdx.x + 1]);
}

// ---------------- kernel: transpose codebook to [d][c] (refine uses it) ----------------
__global__ __launch_bounds__(256)
void btrans_kernel(const float* __restrict__ cb_top, const float* __restrict__ cb_bot) {
    __shared__ float s[32][33];
    int lvl = blockIdx.z;
    const float* cb = lvl ? cb_bot : cb_top;
    int c0 = blockIdx.x * 32, d0 = blockIdx.y * 32;
    int lx = threadIdx.x & 31, ly = threadIdx.x >> 5;
#pragma unroll
    for (int k = 0; k < 4; k++)
        s[ly + 8 * k][lx] = cb[(size_t)(c0 + ly + 8 * k) * DIM + d0 + lx];
    __syncthreads();
#pragma unroll
    for (int k = 0; k < 4; k++)
        g_bt[((size_t)lvl * DIM + d0 + ly + 8 * k) * KCODES + c0 + lx] = s[lx][ly + 8 * k];
}

// ---------------- argmin GEMM: x.e_hi on tensor pipe (2 GEMMs), persistent CTAs ----------------
// smem: A_hi 32KB | A_lo 32KB | B ring 4 x 4KB (e_hi only, 32B rows, XOR swizzle) => 80KB/CTA
#define SM_AHI 0
#define SM_ALO 32768
#define SM_B   65536
#define SM_RED 65536             // reduce scratch reuses B ring after mainloop
#define ARG_SMEM (65536 + 4 * 4096)

__device__ __forceinline__ void issueB(char* smem, int s, int tid, size_t L) {
    int nt = s >> 4, ch = s & 15, buf = s & 3;
    int row = tid >> 1, sg = tid & 1;
    char* bb = smem + SM_B + buf * 4096;
    size_t src = (L + nt * 128 + row) * (size_t)128 + ch * 8 + sg * 4;
    cp16(bb + row * 32 + ((sg ^ ((row >> 2) & 1)) << 4), &g_ehi[src]);
    CP_COMMIT();
}

__global__ __launch_bounds__(256, 2)
void argmin_kernel() {
    extern __shared__ __align__(128) char smem[];
    __shared__ int s_pos;
    int tid = threadIdx.x, lane = tid & 31, wid = tid >> 5;
    int wm = wid >> 2, wn = wid & 3;           // 2 warp-rows (32M) x 4 warp-cols (32N)
    uint32_t sb = (uint32_t)__cvta_generic_to_shared(smem);

    for (;;) {
        if (tid == 0) s_pos = atomicAdd(&g_tile_ctr, 1);
        __syncthreads();
        int pos = s_pos;
        if (pos >= NTILES) break;
        int lvl = pos >> 9;
        int m0 = (pos & 511) * 64;
        size_t XL = (size_t)lvl * NPTS;
        size_t EL = (size_t)lvl * KCODES;

        // ---- prologue: A (hi+lo, 64 rows) resident swizzled smem; then B chunks 0..2 ----
#pragma unroll
        for (int i = 0; i < 8; i++) {
            int idx = tid + i * 256;
            int row = idx >> 5, seg = idx & 31;
            int soff = ((seg ^ (row & 7)) << 4);
            size_t src = (XL + m0 + row) * (size_t)128 + seg * 4;
            cp16(smem + SM_AHI + row * 512 + soff, &g_xhi[src]);
            cp16(smem + SM_ALO + row * 512 + soff, &g_xlo[src]);
        }
        CP_COMMIT();
        issueB(smem, 0, tid, EL);
        issueB(smem, 1, tid, EL);
        issueB(smem, 2, tid, EL);

        float tb[4], t2[4];
        int   ti[4];
#pragma unroll
        for (int r = 0; r < 4; r++) { tb[r] = -FLT_MAX; t2[r] = -FLT_MAX; ti[r] = 0; }

#pragma unroll 1
        for (int nt = 0; nt < 8; nt++) {
            float acc[2][4][4];
#pragma unroll
            for (int j = 0; j < 4; j++) {
                int c0 = nt * 128 + wn * 32 + j * 8 + (lane & 3) * 2;
                float2 ci = g_cninit[lvl * (KCODES / 2) + (c0 >> 1)];
#pragma unroll
                for (int mi = 0; mi < 2; mi++) {
                    acc[mi][j][0] = ci.x; acc[mi][j][1] = ci.y;
                    acc[mi][j][2] = ci.x; acc[mi][j][3] = ci.y;
                }
            }

#pragma unroll 1
            for (int ch = 0; ch < 16; ch++) {
                int s = nt * 16 + ch;
                if (s < 125) CP_WAIT2();
                else         CP_WAIT0();
                __syncthreads();
                if (s < 125) issueB(smem, s + 3, tid, EL);
                uint32_t bb = sb + SM_B + (s & 3) * 4096;

                uint32_t ah[2][4], al[2][4];
#pragma unroll
                for (int mi = 0; mi < 2; mi++) {
                    int p = wm * 32 + mi * 16 + (lane & 7) + ((lane >> 3) & 1) * 8;
                    int seg = ch * 2 + (lane >> 4);
                    uint32_t off = p * 512 + ((seg ^ (p & 7)) << 4);
                    lda4(ah[mi], sb + SM_AHI + off);
                    lda4(al[mi], sb + SM_ALO + off);
                }

                uint32_t bh[8];
                {
                    int g = lane >> 3, i = lane & 7;
                    int row0 = wn * 32 + (g >> 1) * 8 + i;
                    int row1 = row0 + 16;
                    uint32_t a0 = bb + row0 * 32 + (((g & 1) ^ ((row0 >> 2) & 1)) << 4);
                    uint32_t a1 = bb + row1 * 32 + (((g & 1) ^ ((row1 >> 2) & 1)) << 4);
                    lda4(&bh[0], a0);
                    lda4(&bh[4], a1);
                }
#pragma unroll
                for (int j = 0; j < 4; j++) {
#pragma unroll
                    for (int mi = 0; mi < 2; mi++) {
                        mma16816(acc[mi][j], ah[mi], &bh[2 * j]);
                        mma16816(acc[mi][j], al[mi], &bh[2 * j]);
                    }
                }
            }

#pragma unroll
            for (int j = 0; j < 4; j++) {
                int cbase = nt * 128 + wn * 32 + j * 8 + (lane & 3) * 2;
#pragma unroll
                for (int mi = 0; mi < 2; mi++)
#pragma unroll
                    for (int rh = 0; rh < 2; rh++) {
                        int r = mi * 2 + rh;
#pragma unroll
                        for (int cc = 0; cc < 2; cc++) {
                            float v = acc[mi][j][rh * 2 + cc];
                            int c = cbase + cc;
                            if (v > tb[r]) { t2[r] = tb[r]; tb[r] = v; ti[r] = c; }
                            else if (v > t2[r]) t2[r] = v;
                        }
                    }
            }
        }

#pragma unroll
        for (int k = 1; k <= 2; k <<= 1) {
#pragma unroll
            for (int r = 0; r < 4; r++) {
                float ob = __shfl_xor_sync(0xffffffffu, tb[r], k);
                float o2 = __shfl_xor_sync(0xffffffffu, t2[r], k);
                int   oi = __shfl_xor_sync(0xffffffffu, ti[r], k);
                if (ob > tb[r] || (ob == tb[r] && oi < ti[r])) {
                    t2[r] = fmaxf(tb[r], o2); tb[r] = ob; ti[r] = oi;
                } else {
                    t2[r] = fmaxf(t2[r], ob);
                }
            }
        }

        __syncthreads();
        float* rv  = (float*)(smem + SM_RED);
        float* r2v = rv + 256;
        int*   rix = (int*)(r2v + 256);
        if ((lane & 3) == 0) {
#pragma unroll
            for (int r = 0; r < 4; r++) {
                int row = wm * 32 + (r >> 1) * 16 + (r & 1) * 8 + (lane >> 2);
                rv[row * 4 + wn]  = tb[r];
                r2v[row * 4 + wn] = t2[r];
                rix[row * 4 + wn] = ti[r];
            }
        }
        __syncthreads();
        if (tid < 64) {
            float bv = rv[tid * 4];
            float bs = r2v[tid * 4];
            int   bi = rix[tid * 4];
#pragma unroll
            for (int x = 1; x < 4; x++) {
                float v  = rv[tid * 4 + x];
                float v2 = r2v[tid * 4 + x];
                int   ii = rix[tid * 4 + x];
                if (v > bv || (v == bv && ii < bi)) { bs = fmaxf(bv, v2); bv = v; bi = ii; }
                else                                 bs = fmaxf(bs, v);
            }
            g_idx[lvl][m0 + tid] = bi;
            if (bv - bs < TAU_S) {
                int p2 = atomicAdd(&g_refine_count[lvl], 1);
                g_refine_list[lvl][p2] = m0 + tid;
            }
        }
    }
}

// ---------------- kernel: two-stage refinement (f32 re-rank, exact only for ties) ----------------
__global__ __launch_bounds__(1024)
void refine_kernel(const float* __restrict__ h_top, const float* __restrict__ h_bot) {
    int lvl = blockIdx.y;
    const float* h = lvl ? h_bot : h_top;
    const float* bt = g_bt + (size_t)lvl * DIM * KCODES;
    int cnt = g_refine_count[lvl];

    __shared__ float xs[DIM];
    __shared__ float rh[1024], rl[1024];
    __shared__ int   rix[1024];

    int tid = threadIdx.x;
    int c = tid;                                // one code per thread

    for (int e = blockIdx.x; e < cnt; e += gridDim.x) {
        int p = g_refine_list[lvl][e];
        int b = p / TLEN, t = p % TLEN;
        __syncthreads();   // protect xs/reduce arrays across outer iterations
        if (tid < DIM)
            xs[tid] = h[((size_t)b * DIM + tid) * TLEN + t];
        __syncthreads();

        // ---- stage A: plain-f32 distance (cheap re-rank) ----
        float dv = 0.f;
#pragma unroll 8
        for (int d = 0; d < DIM; d++) {
            float diff = xs[d] - bt[(size_t)d * KCODES + c];
            dv = fmaf(diff, diff, dv);
        }
        rh[tid] = dv; rix[tid] = c;
        __syncthreads();
#pragma unroll
        for (int s = 512; s; s >>= 1) {
            if (tid < s) {
                float ov = rh[tid + s];
                int   oi = rix[tid + s];
                if (ov < rh[tid] || (ov == rh[tid] && oi < rix[tid])) { rh[tid] = ov; rix[tid] = oi; }
            }
            __syncthreads();
        }
        float bestA = rh[0];
        int   bestiA = rix[0];
        __syncthreads();
        rh[tid] = (c == bestiA) ? FLT_MAX : dv;
        __syncthreads();
#pragma unroll
        for (int s = 512; s; s >>= 1) {
            if (tid < s) rh[tid] = fminf(rh[tid], rh[tid + s]);
            __syncthreads();
        }
        float secondA = rh[0];
        __syncthreads();

        if (secondA - bestA >= TAU_EXACT) {      // block-uniform branch
            if (tid == 0) g_idx[lvl][p] = bestiA;
            continue;
        }

        // ---- stage B: compensated double-f32 exact (rare) ----
        float hi = 0.f, lo = 0.f;
#pragma unroll 8
        for (int d = 0; d < DIM; d++) {
            float ev = bt[(size_t)d * KCODES + c];
            float x  = xs[d];
            float s  = x - ev;
            float bb = s - x;
            float err = (x - (s - bb)) + ((-ev) - bb);
            float pq = s * s;
            float pe = fmaf(s, s, -pq);
            float cross = fmaf(2.f * s, err, fmaf(err, err, pe));
            float t1  = hi + pq;
            float bb2 = t1 - hi;
            float e2  = (hi - (t1 - bb2)) + (pq - bb2);
            hi = t1;
            lo += e2 + cross;
        }
        float th = hi + lo;
        float tl = lo - (th - hi);

        rh[tid] = th; rl[tid] = tl; rix[tid] = c;
        __syncthreads();
#pragma unroll
        for (int s = 512; s; s >>= 1) {
            if (tid < s) {
                float oh = rh[tid + s], ol = rl[tid + s];
                int   oi = rix[tid + s];
                float mh = rh[tid], ml = rl[tid];
                int   mi = rix[tid];
                if (oh < mh || (oh == mh && (ol < ml || (ol == ml && oi < mi)))) {
                    rh[tid] = oh; rl[tid] = ol; rix[tid] = oi;
                }
            }
            __syncthreads();
        }
        if (tid == 0) g_idx[lvl][p] = rix[0];
    }
}

// ---------------- kernel: gather z_q + per-block loss partials ----------------
__global__ __launch_bounds__(256)
void gather_kernel(const float* __restrict__ h_top, const float* __restrict__ h_bot,
                   const float* __restrict__ cb_top, const float* __restrict__ cb_bot,
                   float* __restrict__ out) {
    int lvl = blockIdx.z;
    const float* h  = lvl ? h_bot  : h_top;
    const float* cb = lvl ? cb_bot : cb_top;
    float* z = out + (size_t)lvl * NELEM;

    int b = blockIdx.y;
    int t0 = blockIdx.x * 32;
    int tid = threadIdx.x;

    __shared__ int   sidx[32];
    __shared__ float sh[32 * 33];
    __shared__ float red[256];

    if (tid < 32) sidx[tid] = g_idx[lvl][b * TLEN + t0 + tid];
    __syncthreads();

    float lacc = 0.f;
    int j2 = tid >> 3, l8 = tid & 7;

    for (int dc = 0; dc < DIM; dc += 32) {
        float4 v = *(const float4*)(cb + (size_t)sidx[j2] * DIM + dc + l8 * 4);
        sh[(l8 * 4 + 0) * 33 + j2] = v.x;
        sh[(l8 * 4 + 1) * 33 + j2] = v.y;
        sh[(l8 * 4 + 2) * 33 + j2] = v.z;
        sh[(l8 * 4 + 3) * 33 + j2] = v.w;
        __syncthreads();
#pragma unroll
        for (int it = 0; it < 4; it++) {
            int i = tid + it * 256;
            int dl = i >> 5, j = i & 31;
            size_t off = ((size_t)b * DIM + dc + dl) * TLEN + t0 + j;
            float zz = sh[dl * 33 + j];
            z[off] = zz;
            float e = h[off] - zz;
            lacc = fmaf(e, e, lacc);
        }
        __syncthreads();
    }

    red[tid] = lacc;
    __syncthreads();
#pragma unroll
    for (int s = 128; s; s >>= 1) {
        if (tid < s) red[tid] += red[tid + s];
        __syncthreads();
    }
    if (tid == 0) g_partial[lvl][blockIdx.y * (TLEN / 32) + blockIdx.x] = red[0];
}

// ---------------- kernel: finalize scalars ----------------
__global__ __launch_bounds__(1024)
void finalize_kernel(float* __restrict__ out) {
    __shared__ int   hist[KCODES];
    __shared__ float red[1024];
    int tid = threadIdx.x;

    float sums[2];
#pragma unroll
    for (int lvl = 0; lvl < 2; lvl++) {
        red[tid] = g_partial[lvl][tid];
        __syncthreads();
        for (int s = 512; s; s >>= 1) {
            if (tid < s) red[tid] += red[tid + s];
            __syncthreads();
        }
        sums[lvl] = red[0];
        __syncthreads();
    }
    float loss = sums[0] * (1.f / (float)NELEM) + sums[1] * (1.f / (float)NELEM);

    float ppl[2];
#pragma unroll
    for (int lvl = 0; lvl < 2; lvl++) {
        hist[tid] = 0;
        __syncthreads();
#pragma unroll
        for (int i = 0; i < NPTS / 1024; i++)
            atomicAdd(&hist[g_idx[lvl][i * 1024 + tid]], 1);
        __syncthreads();
        float p = (float)hist[tid] * (1.f / (float)NPTS);
        red[tid] = p * logf(p + 1e-10f);
        __syncthreads();
        for (int s = 512; s; s >>= 1) {
            if (tid < s) red[tid] += red[tid + s];
            __syncthreads();
        }
        ppl[lvl] = expf(-red[0]);
        __syncthreads();
    }

    if (tid == 0) {
        size_t base = (size_t)2 * NELEM;
        out[base + 0] = loss;
        out[base + 1] = loss;
        out[base + 2] = ppl[0];
        out[base + 3] = ppl[1];
    }
}

// ---------------- launcher ----------------
extern "C" void kernel_launch(void* const* d_in, const int* in_sizes, int n_in,
                              void* d_out, int out_size) {
    const float* h_top  = (const float*)d_in[0];
    const float* h_bot  = (const float*)d_in[1];
    const float* cb_top = (const float*)d_in[2];
    const float* cb_bot = (const float*)d_in[3];
    float* out = (float*)d_out;

    cudaFuncSetAttribute(argmin_kernel,
                         cudaFuncAttributeMaxDynamicSharedMemorySize, ARG_SMEM);

    xsplit_kernel<<<dim3(TLEN / 32, DIM / 64, BATCH * LEVELS), 256>>>(h_top, h_bot);
    ecnorm_kernel<<<dim3(KCODES / 8, LEVELS), 256>>>(cb_top, cb_bot);
    btrans_kernel<<<dim3(KCODES / 32, DIM / 32, LEVELS), 256>>>(cb_top, cb_bot);
    argmin_kernel<<<296, 256, ARG_SMEM>>>();
    refine_kernel<<<dim3(512, LEVELS), 1024>>>(h_top, h_bot);
    gather_kernel<<<dim3(TLEN / 32, BATCH, LEVELS), 256>>>(h_top, h_bot, cb_top, cb_bot, out);
    finalize_kernel<<<1, 1024>>>(out);
}

// round 16
// speedup vs baseline: 1.5587x; 1.0744x over previous
#include <cuda_runtime.h>
#include <cuda_bf16.h>
#include <cstdint>
#include <cfloat>

#define LEVELS 2
#define BATCH  16
#define DIM    256
#define TLEN   2048
#define NPTS   (BATCH * TLEN)       // 32768 points per level
#define KCODES 1024
#define NELEM  (BATCH * DIM * TLEN) // 8388608 per level
#define GATHER_BLOCKS (BATCH * (TLEN / 32))
#define TAU_S  0.25f                // 10x sigma of dropped x.e_lo term (sigma~0.025)
#define TAU_EXACT 0.03f             // 30x RMS of plain-f32 stage-A distance error
#define NTILES (LEVELS * (NPTS / 64))   // 1024 work items

// ---------------- scratch (no allocations allowed) ----------------
__device__ float    g_bt[(size_t)LEVELS * DIM * KCODES];   // codebook transposed (refine)
__device__ float2   g_cninit[LEVELS * (KCODES / 2)];       // packed (-cn/2) pairs
__device__ float    g_partial[LEVELS][GATHER_BLOCKS];
__device__ int      g_idx[LEVELS][NPTS];
__device__ int      g_refine_count[LEVELS];
__device__ int      g_refine_list[LEVELS][NPTS];
__device__ int      g_tile_ctr;
// bf16 splits packed as u32 pairs (elem 2d in low half): [p][d] and [c][d]
__device__ unsigned g_xhi[(size_t)LEVELS * NPTS * (DIM / 2)];
__device__ unsigned g_xlo[(size_t)LEVELS * NPTS * (DIM / 2)];
__device__ unsigned g_ehi[(size_t)LEVELS * KCODES * (DIM / 2)];

// ---------------- helpers ----------------
__device__ __forceinline__ void cp16(void* dst, const void* src) {
    unsigned s = (unsigned)__cvta_generic_to_shared(dst);
    asm volatile("cp.async.cg.shared.global [%0], [%1], 16;" :: "r"(s), "l"(src) : "memory");
}
#define CP_COMMIT() asm volatile("cp.async.commit_group;" ::: "memory")
#define CP_WAIT2()  asm volatile("cp.async.wait_group 2;" ::: "memory")
#define CP_WAIT0()  asm volatile("cp.async.wait_group 0;" ::: "memory")

__device__ __forceinline__ void lda4(uint32_t r[4], uint32_t addr) {
    asm volatile("ldmatrix.sync.aligned.m8n8.x4.shared.b16 {%0,%1,%2,%3}, [%4];"
                 : "=r"(r[0]), "=r"(r[1]), "=r"(r[2]), "=r"(r[3]) : "r"(addr));
}
__device__ __forceinline__ void mma16816(float d[4], const uint32_t a[4], const uint32_t b[2]) {
    asm volatile("mma.sync.aligned.m16n8k16.row.col.f32.bf16.bf16.f32 "
                 "{%0,%1,%2,%3}, {%4,%5,%6,%7}, {%8,%9}, {%0,%1,%2,%3};"
                 : "+f"(d[0]), "+f"(d[1]), "+f"(d[2]), "+f"(d[3])
                 : "r"(a[0]), "r"(a[1]), "r"(a[2]), "r"(a[3]), "r"(b[0]), "r"(b[1]));
}
// packed f32x2 helpers (refine stage A)
__device__ __forceinline__ unsigned long long pk2(float a) {
    unsigned long long r;
    unsigned int u = __float_as_uint(a);
    asm("mov.b64 %0, {%1, %1};" : "=l"(r) : "r"(u));
    return r;
}
__device__ __forceinline__ void fma2acc(unsigned long long& acc,
                                        unsigned long long a, unsigned long long b) {
    asm("fma.rn.f32x2 %0, %1, %2, %0;" : "+l"(acc) : "l"(a), "l"(b));
}
__device__ __forceinline__ unsigned long long fma2o(unsigned long long a,
                                                    unsigned long long b,
                                                    unsigned long long c) {
    unsigned long long d;
    asm("fma.rn.f32x2 %0, %1, %2, %3;" : "=l"(d) : "l"(a), "l"(b), "l"(c));
    return d;
}
__device__ __forceinline__ void unpk2(unsigned long long v, float& lo, float& hi) {
    unsigned int l, h;
    asm("mov.b64 {%0, %1}, %2;" : "=r"(l), "=r"(h) : "l"(v));
    lo = __uint_as_float(l);
    hi = __uint_as_float(h);
}

// ---------------- kernel: split+transpose h -> x_hi/x_lo bf16 [lvl][p][d] ----------------
__global__ __launch_bounds__(256)
void xsplit_kernel(const float* __restrict__ h_top, const float* __restrict__ h_bot) {
    __shared__ float s[32][65];
    int z = blockIdx.z, lvl = z >> 4, b = z & 15;
    const float* h = lvl ? h_bot : h_top;
    int t0 = blockIdx.x * 32, d0 = blockIdx.y * 64;
    int tid = threadIdx.x, lane = tid & 31, w = tid >> 5;
#pragma unroll
    for (int k = 0; k < 8; k++) {
        int dl = w + 8 * k;
        s[lane][dl] = h[((size_t)b * DIM + d0 + dl) * TLEN + t0 + lane];
    }
    __syncthreads();
    int pl = tid >> 3, q = tid & 7;
    int p = b * TLEN + t0 + pl;
    size_t rowbase = ((size_t)lvl * NPTS + p) * (DIM / 2) + (d0 >> 1);
#pragma unroll
    for (int k = 0; k < 4; k++) {
        int d2 = q + 8 * k;
        float v0 = s[pl][2 * d2], v1 = s[pl][2 * d2 + 1];
        __nv_bfloat16 h0 = __float2bfloat16(v0), h1 = __float2bfloat16(v1);
        __nv_bfloat16 l0 = __float2bfloat16(v0 - __bfloat162float(h0));
        __nv_bfloat16 l1 = __float2bfloat16(v1 - __bfloat162float(h1));
        g_xhi[rowbase + d2] = ((unsigned)__bfloat16_as_ushort(h1) << 16) | __bfloat16_as_ushort(h0);
        g_xlo[rowbase + d2] = ((unsigned)__bfloat16_as_ushort(l1) << 16) | __bfloat16_as_ushort(l0);
    }
}

// ---------------- kernel: codebook split (hi only) + (-cn/2) + counter resets ----------------
__global__ __launch_bounds__(256)
void ecnorm_kernel(const float* __restrict__ cb_top, const float* __restrict__ cb_bot) {
    __shared__ float s8[8];
    int lvl = blockIdx.y;
    if (blockIdx.x == 0 && threadIdx.x == 0) {
        g_refine_count[lvl] = 0;
        if (lvl == 0) g_tile_ctr = 0;
    }
    const float* cb = lvl ? cb_bot : cb_top;
    int w = threadIdx.x >> 5, lane = threadIdx.x & 31;
    int c = blockIdx.x * 8 + w;
    const float* row = cb + (size_t)c * DIM;
    size_t rowbase = ((size_t)lvl * KCODES + c) * (DIM / 2);
    float sacc = 0.f;
#pragma unroll
    for (int k = 0; k < 4; k++) {
        int d2 = lane + 32 * k;
        float v0 = row[2 * d2], v1 = row[2 * d2 + 1];
        sacc = fmaf(v0, v0, sacc);
        sacc = fmaf(v1, v1, sacc);
        __nv_bfloat16 h0 = __float2bfloat16(v0), h1 = __float2bfloat16(v1);
        g_ehi[rowbase + d2] = ((unsigned)__bfloat16_as_ushort(h1) << 16) | __bfloat16_as_ushort(h0);
    }
#pragma unroll
    for (int o = 16; o; o >>= 1) sacc += __shfl_down_sync(0xffffffffu, sacc, o);
    if (lane == 0) s8[w] = sacc;
    __syncthreads();
    if (threadIdx.x < 4)
        g_cninit[lvl * (KCODES / 2) + blockIdx.x * 4 + threadIdx.x] =
            make_float2(-0.5f * s8[2 * threadIdx.x], -0.5f * s8[2 * threadIdx.x + 1]);
}

// ---------------- kernel: transpose codebook to [d][c] (refine uses it) ----------------
__global__ __launch_bounds__(256)
void btrans_kernel(const float* __restrict__ cb_top, const float* __restrict__ cb_bot) {
    __shared__ float s[32][33];
    int lvl = blockIdx.z;
    const float* cb = lvl ? cb_bot : cb_top;
    int c0 = blockIdx.x * 32, d0 = blockIdx.y * 32;
    int lx = threadIdx.x & 31, ly = threadIdx.x >> 5;
#pragma unroll
    for (int k = 0; k < 4; k++)
        s[ly + 8 * k][lx] = cb[(size_t)(c0 + ly + 8 * k) * DIM + d0 + lx];
    __syncthreads();
#pragma unroll
    for (int k = 0; k < 4; k++)
        g_bt[((size_t)lvl * DIM + d0 + ly + 8 * k) * KCODES + c0 + lx] = s[lx][ly + 8 * k];
}

// ---------------- argmin GEMM: x.e_hi on tensor pipe (2 GEMMs), persistent CTAs ----------------
// smem: A_hi 32KB | A_lo 32KB | B ring 4 x 4KB (e_hi only, 32B rows, XOR swizzle) => 80KB/CTA
#define SM_AHI 0
#define SM_ALO 32768
#define SM_B   65536
#define SM_RED 65536             // reduce scratch reuses B ring after mainloop
#define ARG_SMEM (65536 + 4 * 4096)

__device__ __forceinline__ void issueB(char* smem, int s, int tid, size_t L) {
    int nt = s >> 4, ch = s & 15, buf = s & 3;
    int row = tid >> 1, sg = tid & 1;
    char* bb = smem + SM_B + buf * 4096;
    size_t src = (L + nt * 128 + row) * (size_t)128 + ch * 8 + sg * 4;
    cp16(bb + row * 32 + ((sg ^ ((row >> 2) & 1)) << 4), &g_ehi[src]);
    CP_COMMIT();
}

__global__ __launch_bounds__(256, 2)
void argmin_kernel() {
    extern __shared__ __align__(128) char smem[];
    __shared__ int s_pos;
    int tid = threadIdx.x, lane = tid & 31, wid = tid >> 5;
    int wm = wid >> 2, wn = wid & 3;           // 2 warp-rows (32M) x 4 warp-cols (32N)
    uint32_t sb = (uint32_t)__cvta_generic_to_shared(smem);

    for (;;) {
        if (tid == 0) s_pos = atomicAdd(&g_tile_ctr, 1);
        __syncthreads();
        int pos = s_pos;
        if (pos >= NTILES) break;
        int lvl = pos >> 9;
        int m0 = (pos & 511) * 64;
        size_t XL = (size_t)lvl * NPTS;
        size_t EL = (size_t)lvl * KCODES;

#pragma unroll
        for (int i = 0; i < 8; i++) {
            int idx = tid + i * 256;
            int row = idx >> 5, seg = idx & 31;
            int soff = ((seg ^ (row & 7)) << 4);
            size_t src = (XL + m0 + row) * (size_t)128 + seg * 4;
            cp16(smem + SM_AHI + row * 512 + soff, &g_xhi[src]);
            cp16(smem + SM_ALO + row * 512 + soff, &g_xlo[src]);
        }
        CP_COMMIT();
        issueB(smem, 0, tid, EL);
        issueB(smem, 1, tid, EL);
        issueB(smem, 2, tid, EL);

        float tb[4], t2[4];
        int   ti[4];
#pragma unroll
        for (int r = 0; r < 4; r++) { tb[r] = -FLT_MAX; t2[r] = -FLT_MAX; ti[r] = 0; }

#pragma unroll 1
        for (int nt = 0; nt < 8; nt++) {
            float acc[2][4][4];
#pragma unroll
            for (int j = 0; j < 4; j++) {
                int c0 = nt * 128 + wn * 32 + j * 8 + (lane & 3) * 2;
                float2 ci = g_cninit[lvl * (KCODES / 2) + (c0 >> 1)];
#pragma unroll
                for (int mi = 0; mi < 2; mi++) {
                    acc[mi][j][0] = ci.x; acc[mi][j][1] = ci.y;
                    acc[mi][j][2] = ci.x; acc[mi][j][3] = ci.y;
                }
            }

#pragma unroll 1
            for (int ch = 0; ch < 16; ch++) {
                int s = nt * 16 + ch;
                if (s < 125) CP_WAIT2();
                else         CP_WAIT0();
                __syncthreads();
                if (s < 125) issueB(smem, s + 3, tid, EL);
                uint32_t bb = sb + SM_B + (s & 3) * 4096;

                uint32_t ah[2][4], al[2][4];
#pragma unroll
                for (int mi = 0; mi < 2; mi++) {
                    int p = wm * 32 + mi * 16 + (lane & 7) + ((lane >> 3) & 1) * 8;
                    int seg = ch * 2 + (lane >> 4);
                    uint32_t off = p * 512 + ((seg ^ (p & 7)) << 4);
                    lda4(ah[mi], sb + SM_AHI + off);
                    lda4(al[mi], sb + SM_ALO + off);
                }

                uint32_t bh[8];
                {
                    int g = lane >> 3, i = lane & 7;
                    int row0 = wn * 32 + (g >> 1) * 8 + i;
                    int row1 = row0 + 16;
                    uint32_t a0 = bb + row0 * 32 + (((g & 1) ^ ((row0 >> 2) & 1)) << 4);
                    uint32_t a1 = bb + row1 * 32 + (((g & 1) ^ ((row1 >> 2) & 1)) << 4);
                    lda4(&bh[0], a0);
                    lda4(&bh[4], a1);
                }
#pragma unroll
                for (int j = 0; j < 4; j++) {
#pragma unroll
                    for (int mi = 0; mi < 2; mi++) {
                        mma16816(acc[mi][j], ah[mi], &bh[2 * j]);
                        mma16816(acc[mi][j], al[mi], &bh[2 * j]);
                    }
                }
            }

#pragma unroll
            for (int j = 0; j < 4; j++) {
                int cbase = nt * 128 + wn * 32 + j * 8 + (lane & 3) * 2;
#pragma unroll
                for (int mi = 0; mi < 2; mi++)
#pragma unroll
                    for (int rh = 0; rh < 2; rh++) {
                        int r = mi * 2 + rh;
#pragma unroll
                        for (int cc = 0; cc < 2; cc++) {
                            float v = acc[mi][j][rh * 2 + cc];
                            int c = cbase + cc;
                            if (v > tb[r]) { t2[r] = tb[r]; tb[r] = v; ti[r] = c; }
                            else if (v > t2[r]) t2[r] = v;
                        }
                    }
            }
        }

#pragma unroll
        for (int k = 1; k <= 2; k <<= 1) {
#pragma unroll
            for (int r = 0; r < 4; r++) {
                float ob = __shfl_xor_sync(0xffffffffu, tb[r], k);
                float o2 = __shfl_xor_sync(0xffffffffu, t2[r], k);
                int   oi = __shfl_xor_sync(0xffffffffu, ti[r], k);
                if (ob > tb[r] || (ob == tb[r] && oi < ti[r])) {
                    t2[r] = fmaxf(tb[r], o2); tb[r] = ob; ti[r] = oi;
                } else {
                    t2[r] = fmaxf(t2[r], ob);
                }
            }
        }

        __syncthreads();
        float* rv  = (float*)(smem + SM_RED);
        float* r2v = rv + 256;
        int*   rix = (int*)(r2v + 256);
        if ((lane & 3) == 0) {
#pragma unroll
            for (int r = 0; r < 4; r++) {
                int row = wm * 32 + (r >> 1) * 16 + (r & 1) * 8 + (lane >> 2);
                rv[row * 4 + wn]  = tb[r];
                r2v[row * 4 + wn] = t2[r];
                rix[row * 4 + wn] = ti[r];
            }
        }
        __syncthreads();
        if (tid < 64) {
            float bv = rv[tid * 4];
            float bs = r2v[tid * 4];
            int   bi = rix[tid * 4];
#pragma unroll
            for (int x = 1; x < 4; x++) {
                float v  = rv[tid * 4 + x];
                float v2 = r2v[tid * 4 + x];
                int   ii = rix[tid * 4 + x];
                if (v > bv || (v == bv && ii < bi)) { bs = fmaxf(bv, v2); bv = v; bi = ii; }
                else                                 bs = fmaxf(bs, v);
            }
            g_idx[lvl][m0 + tid] = bi;
            if (bv - bs < TAU_S) {
                int p2 = atomicAdd(&g_refine_count[lvl], 1);
                g_refine_list[lvl][p2] = m0 + tid;
            }
        }
    }
}

// ---------------- kernel: batched two-stage refinement ----------------
// Stage A: 8 points per bt sweep, f32x2 packed distances (1 code/thread).
// Stage B: compensated exact, only when stage-A gap < TAU_EXACT.
__global__ __launch_bounds__(1024)
void refine_kernel(const float* __restrict__ h_top, const float* __restrict__ h_bot) {
    int lvl = blockIdx.y;
    const float* h = lvl ? h_bot : h_top;
    const float* bt = g_bt + (size_t)lvl * DIM * KCODES;
    int cnt = g_refine_count[lvl];

    __shared__ __align__(16) float2 xs2[DIM][4];   // 8KB: 4 point-pairs
    __shared__ float rb[1024], rs[1024], rl[1024];
    __shared__ int   rix[1024];
    __shared__ int   plist[8];

    int tid = threadIdx.x;
    int c = tid;

    for (int base = blockIdx.x * 8; base < cnt; base += gridDim.x * 8) {
        int nb = min(8, cnt - base);
        __syncthreads();                            // previous round smem done
        if (tid < 8) plist[tid] = g_refine_list[lvl][base + min(tid, nb - 1)];
        __syncthreads();
        // stage xs (pairs of points packed into float2 lanes)
        {
            int g = tid >> 7, dd = (tid & 127) * 2;
            int p = plist[g];
            int b = p / TLEN, t = p % TLEN;
            float v0 = h[((size_t)b * DIM + dd) * TLEN + t];
            float v1 = h[((size_t)b * DIM + dd + 1) * TLEN + t];
            if (g & 1) { xs2[dd][g >> 1].y = v0; xs2[dd + 1][g >> 1].y = v1; }
            else       { xs2[dd][g >> 1].x = v0; xs2[dd + 1][g >> 1].x = v1; }
        }
        __syncthreads();

        // ---- stage A: packed f32 distances for all 8 points in one bt sweep ----
        unsigned long long dv[4] = {0ull, 0ull, 0ull, 0ull};
        unsigned long long negone = pk2(-1.0f);
#pragma unroll 4
        for (int d = 0; d < DIM; d++) {
            unsigned long long ev2 = pk2(bt[(size_t)d * KCODES + c]);
#pragma unroll
            for (int q = 0; q < 4; q++) {
                unsigned long long x2 = *(const unsigned long long*)&xs2[d][q];
                unsigned long long df = fma2o(ev2, negone, x2);   // x - e (exact)
                fma2acc(dv[q], df, df);
            }
        }
        float d16[8];
#pragma unroll
        for (int q = 0; q < 4; q++) unpk2(dv[q], d16[2 * q], d16[2 * q + 1]);

        for (int g = 0; g < nb; g++) {
            // top-2 tree over 1024 codes
            rb[tid] = d16[g]; rs[tid] = FLT_MAX; rix[tid] = c;
            __syncthreads();
#pragma unroll
            for (int s = 512; s; s >>= 1) {
                if (tid < s) {
                    float ob = rb[tid + s], os = rs[tid + s];
                    int   oi = rix[tid + s];
                    float mb = rb[tid], ms = rs[tid];
                    int   mi = rix[tid];
                    if (ob < mb || (ob == mb && oi < mi)) {
                        rb[tid] = ob; rix[tid] = oi; rs[tid] = fminf(mb, os);
                    } else {
                        rs[tid] = fminf(ms, ob);
                    }
                }
                __syncthreads();
            }
            float bestA = rb[0], secondA = rs[0];
            int   bestiA = rix[0];
            __syncthreads();

            int p = plist[g];
            if (secondA - bestA >= TAU_EXACT) {     // block-uniform
                if (tid == 0) g_idx[lvl][p] = bestiA;
                continue;
            }

            // ---- stage B: compensated double-f32 exact (rare) ----
            int half = g >> 1;
            float hi = 0.f, lo = 0.f;
#pragma unroll 8
            for (int d = 0; d < DIM; d++) {
                float ev = bt[(size_t)d * KCODES + c];
                float x  = (g & 1) ? xs2[d][half].y : xs2[d][half].x;
                float s  = x - ev;
                float bb = s - x;
                float err = (x - (s - bb)) + ((-ev) - bb);
                float pq = s * s;
                float pe = fmaf(s, s, -pq);
                float cross = fmaf(2.f * s, err, fmaf(err, err, pe));
                float t1  = hi + pq;
                float bb2 = t1 - hi;
                float e2  = (hi - (t1 - bb2)) + (pq - bb2);
                hi = t1;
                lo += e2 + cross;
            }
            float th = hi + lo;
            float tl = lo - (th - hi);

            rb[tid] = th; rl[tid] = tl; rix[tid] = c;
            __syncthreads();
#pragma unroll
            for (int s = 512; s; s >>= 1) {
                if (tid < s) {
                    float oh = rb[tid + s], ol = rl[tid + s];
                    int   oi = rix[tid + s];
                    float mh = rb[tid], ml = rl[tid];
                    int   mi = rix[tid];
                    if (oh < mh || (oh == mh && (ol < ml || (ol == ml && oi < mi)))) {
                        rb[tid] = oh; rl[tid] = ol; rix[tid] = oi;
                    }
                }
                __syncthreads();
            }
            if (tid == 0) g_idx[lvl][p] = rix[0];
            __syncthreads();
        }
    }
}

// ---------------- kernel: gather z_q + per-block loss partials ----------------
__global__ __launch_bounds__(256)
void gather_kernel(const float* __restrict__ h_top, const float* __restrict__ h_bot,
                   const float* __restrict__ cb_top, const float* __restrict__ cb_bot,
                   float* __restrict__ out) {
    int lvl = blockIdx.z;
    const float* h  = lvl ? h_bot  : h_top;
    const float* cb = lvl ? cb_bot : cb_top;
    float* z = out + (size_t)lvl * NELEM;

    int b = blockIdx.y;
    int t0 = blockIdx.x * 32;
    int tid = threadIdx.x;

    __shared__ int   sidx[32];
    __shared__ float sh[32 * 33];
    __shared__ float red[256];

    if (tid < 32) sidx[tid] = g_idx[lvl][b * TLEN + t0 + tid];
    __syncthreads();

    float lacc = 0.f;
    int j2 = tid >> 3, l8 = tid & 7;

    for (int dc = 0; dc < DIM; dc += 32) {
        float4 v = *(const float4*)(cb + (size_t)sidx[j2] * DIM + dc + l8 * 4);
        sh[(l8 * 4 + 0) * 33 + j2] = v.x;
        sh[(l8 * 4 + 1) * 33 + j2] = v.y;
        sh[(l8 * 4 + 2) * 33 + j2] = v.z;
        sh[(l8 * 4 + 3) * 33 + j2] = v.w;
        __syncthreads();
#pragma unroll
        for (int it = 0; it < 4; it++) {
            int i = tid + it * 256;
            int dl = i >> 5, j = i & 31;
            size_t off = ((size_t)b * DIM + dc + dl) * TLEN + t0 + j;
            float zz = sh[dl * 33 + j];
            z[off] = zz;
            float e = h[off] - zz;
            lacc = fmaf(e, e, lacc);
        }
        __syncthreads();
    }

    red[tid] = lacc;
    __syncthreads();
#pragma unroll
    for (int s = 128; s; s >>= 1) {
        if (tid < s) red[tid] += red[tid + s];
        __syncthreads();
    }
    if (tid == 0) g_partial[lvl][blockIdx.y * (TLEN / 32) + blockIdx.x] = red[0];
}

// ---------------- kernel: finalize scalars ----------------
__global__ __launch_bounds__(1024)
void finalize_kernel(float* __restrict__ out) {
    __shared__ int   hist[KCODES];
    __shared__ float red[1024];
    int tid = threadIdx.x;

    float sums[2];
#pragma unroll
    for (int lvl = 0; lvl < 2; lvl++) {
        red[tid] = g_partial[lvl][tid];
        __syncthreads();
        for (int s = 512; s; s >>= 1) {
            if (tid < s) red[tid] += red[tid + s];
            __syncthreads();
        }
        sums[lvl] = red[0];
        __syncthreads();
    }
    float loss = sums[0] * (1.f / (float)NELEM) + sums[1] * (1.f / (float)NELEM);

    float ppl[2];
#pragma unroll
    for (int lvl = 0; lvl < 2; lvl++) {
        hist[tid] = 0;
        __syncthreads();
#pragma unroll
        for (int i = 0; i < NPTS / 1024; i++)
            atomicAdd(&hist[g_idx[lvl][i * 1024 + tid]], 1);
        __syncthreads();
        float p = (float)hist[tid] * (1.f / (float)NPTS);
        red[tid] = p * logf(p + 1e-10f);
        __syncthreads();
        for (int s = 512; s; s >>= 1) {
            if (tid < s) red[tid] += red[tid + s];
            __syncthreads();
        }
        ppl[lvl] = expf(-red[0]);
        __syncthreads();
    }

    if (tid == 0) {
        size_t base = (size_t)2 * NELEM;
        out[base + 0] = loss;
        out[base + 1] = loss;
        out[base + 2] = ppl[0];
        out[base + 3] = ppl[1];
    }
}

// ---------------- launcher ----------------
extern "C" void kernel_launch(void* const* d_in, const int* in_sizes, int n_in,
                              void* d_out, int out_size) {
    const float* h_top  = (const float*)d_in[0];
    const float* h_bot  = (const float*)d_in[1];
    const float* cb_top = (const float*)d_in[2];
    const float* cb_bot = (const float*)d_in[3];
    float* out = (float*)d_out;

    cudaFuncSetAttribute(argmin_kernel,
                         cudaFuncAttributeMaxDynamicSharedMemorySize, ARG_SMEM);

    xsplit_kernel<<<dim3(TLEN / 32, DIM / 64, BATCH * LEVELS), 256>>>(h_top, h_bot);
    ecnorm_kernel<<<dim3(KCODES / 8, LEVELS), 256>>>(cb_top, cb_bot);
    btrans_kernel<<<dim3(KCODES / 32, DIM / 32, LEVELS), 256>>>(cb_top, cb_bot);
    argmin_kernel<<<296, 256, ARG_SMEM>>>();
    refine_kernel<<<dim3(256, LEVELS), 1024>>>(h_top, h_bot);
    gather_kernel<<<dim3(TLEN / 32, BATCH, LEVELS), 256>>>(h_top, h_bot, cb_top, cb_bot, out);
    finalize_kernel<<<1, 1024>>>(out);
}

// round 17
// speedup vs baseline: 1.6195x; 1.0390x over previous
#include <cuda_runtime.h>
#include <cuda_bf16.h>
#include <cstdint>
#include <cfloat>

#define LEVELS 2
#define BATCH  16
#define DIM    256
#define TLEN   2048
#define NPTS   (BATCH * TLEN)       // 32768 points per level
#define KCODES 1024
#define NELEM  (BATCH * DIM * TLEN) // 8388608 per level
#define GATHER_BLOCKS (BATCH * (TLEN / 32))
#define TAU_S  0.25f                // 10x sigma of dropped x.e_lo term (sigma~0.025)
#define TAU_EXACT 0.03f             // 30x RMS of plain-f32 stage-A distance error
#define NTILES (LEVELS * (NPTS / 64))   // 1024 work items

// ---------------- scratch (no allocations allowed) ----------------
__device__ float    g_bt[(size_t)LEVELS * DIM * KCODES];   // codebook transposed (refine)
__device__ float2   g_cninit[LEVELS * (KCODES / 2)];       // packed (-cn/2) pairs
__device__ float    g_partial[LEVELS][GATHER_BLOCKS];
__device__ int      g_idx[LEVELS][NPTS];
__device__ int      g_refine_count[LEVELS];
__device__ int      g_refine_list[LEVELS][NPTS];
__device__ int      g_tile_ctr;
// bf16 splits packed as u32 pairs (elem 2d in low half): [p][d] and [c][d]
__device__ unsigned g_xhi[(size_t)LEVELS * NPTS * (DIM / 2)];
__device__ unsigned g_xlo[(size_t)LEVELS * NPTS * (DIM / 2)];
__device__ unsigned g_ehi[(size_t)LEVELS * KCODES * (DIM / 2)];

// ---------------- helpers ----------------
__device__ __forceinline__ void cp16(void* dst, const void* src) {
    unsigned s = (unsigned)__cvta_generic_to_shared(dst);
    asm volatile("cp.async.cg.shared.global [%0], [%1], 16;" :: "r"(s), "l"(src) : "memory");
}
#define CP_COMMIT() asm volatile("cp.async.commit_group;" ::: "memory")
#define CP_WAIT2()  asm volatile("cp.async.wait_group 2;" ::: "memory")
#define CP_WAIT0()  asm volatile("cp.async.wait_group 0;" ::: "memory")

__device__ __forceinline__ void lda4(uint32_t r[4], uint32_t addr) {
    asm volatile("ldmatrix.sync.aligned.m8n8.x4.shared.b16 {%0,%1,%2,%3}, [%4];"
                 : "=r"(r[0]), "=r"(r[1]), "=r"(r[2]), "=r"(r[3]) : "r"(addr));
}
__device__ __forceinline__ void mma16816(float d[4], const uint32_t a[4], const uint32_t b[2]) {
    asm volatile("mma.sync.aligned.m16n8k16.row.col.f32.bf16.bf16.f32 "
                 "{%0,%1,%2,%3}, {%4,%5,%6,%7}, {%8,%9}, {%0,%1,%2,%3};"
                 : "+f"(d[0]), "+f"(d[1]), "+f"(d[2]), "+f"(d[3])
                 : "r"(a[0]), "r"(a[1]), "r"(a[2]), "r"(a[3]), "r"(b[0]), "r"(b[1]));
}
// packed f32x2 helpers (refine stage A)
__device__ __forceinline__ unsigned long long pk2(float a) {
    unsigned long long r;
    unsigned int u = __float_as_uint(a);
    asm("mov.b64 %0, {%1, %1};" : "=l"(r) : "r"(u));
    return r;
}
__device__ __forceinline__ void fma2acc(unsigned long long& acc,
                                        unsigned long long a, unsigned long long b) {
    asm("fma.rn.f32x2 %0, %1, %2, %0;" : "+l"(acc) : "l"(a), "l"(b));
}
__device__ __forceinline__ unsigned long long fma2o(unsigned long long a,
                                                    unsigned long long b,
                                                    unsigned long long c) {
    unsigned long long d;
    asm("fma.rn.f32x2 %0, %1, %2, %3;" : "=l"(d) : "l"(a), "l"(b), "l"(c));
    return d;
}
__device__ __forceinline__ void unpk2(unsigned long long v, float& lo, float& hi) {
    unsigned int l, h;
    asm("mov.b64 {%0, %1}, %2;" : "=r"(l), "=r"(h) : "l"(v));
    lo = __uint_as_float(l);
    hi = __uint_as_float(h);
}

// ---------------- kernel: split+transpose h -> x_hi/x_lo bf16 [lvl][p][d] ----------------
__global__ __launch_bounds__(256)
void xsplit_kernel(const float* __restrict__ h_top, const float* __restrict__ h_bot) {
    __shared__ float s[32][65];
    int z = blockIdx.z, lvl = z >> 4, b = z & 15;
    const float* h = lvl ? h_bot : h_top;
    int t0 = blockIdx.x * 32, d0 = blockIdx.y * 64;
    int tid = threadIdx.x, lane = tid & 31, w = tid >> 5;
#pragma unroll
    for (int k = 0; k < 8; k++) {
        int dl = w + 8 * k;
        s[lane][dl] = h[((size_t)b * DIM + d0 + dl) * TLEN + t0 + lane];
    }
    __syncthreads();
    int pl = tid >> 3, q = tid & 7;
    int p = b * TLEN + t0 + pl;
    size_t rowbase = ((size_t)lvl * NPTS + p) * (DIM / 2) + (d0 >> 1);
#pragma unroll
    for (int k = 0; k < 4; k++) {
        int d2 = q + 8 * k;
        float v0 = s[pl][2 * d2], v1 = s[pl][2 * d2 + 1];
        __nv_bfloat16 h0 = __float2bfloat16(v0), h1 = __float2bfloat16(v1);
        __nv_bfloat16 l0 = __float2bfloat16(v0 - __bfloat162float(h0));
        __nv_bfloat16 l1 = __float2bfloat16(v1 - __bfloat162float(h1));
        g_xhi[rowbase + d2] = ((unsigned)__bfloat16_as_ushort(h1) << 16) | __bfloat16_as_ushort(h0);
        g_xlo[rowbase + d2] = ((unsigned)__bfloat16_as_ushort(l1) << 16) | __bfloat16_as_ushort(l0);
    }
}

// ---------------- kernel: codebook split (hi only) + (-cn/2) + counter resets ----------------
__global__ __launch_bounds__(256)
void ecnorm_kernel(const float* __restrict__ cb_top, const float* __restrict__ cb_bot) {
    __shared__ float s8[8];
    int lvl = blockIdx.y;
    if (blockIdx.x == 0 && threadIdx.x == 0) {
        g_refine_count[lvl] = 0;
        if (lvl == 0) g_tile_ctr = 0;
    }
    const float* cb = lvl ? cb_bot : cb_top;
    int w = threadIdx.x >> 5, lane = threadIdx.x & 31;
    int c = blockIdx.x * 8 + w;
    const float* row = cb + (size_t)c * DIM;
    size_t rowbase = ((size_t)lvl * KCODES + c) * (DIM / 2);
    float sacc = 0.f;
#pragma unroll
    for (int k = 0; k < 4; k++) {
        int d2 = lane + 32 * k;
        float v0 = row[2 * d2], v1 = row[2 * d2 + 1];
        sacc = fmaf(v0, v0, sacc);
        sacc = fmaf(v1, v1, sacc);
        __nv_bfloat16 h0 = __float2bfloat16(v0), h1 = __float2bfloat16(v1);
        g_ehi[rowbase + d2] = ((unsigned)__bfloat16_as_ushort(h1) << 16) | __bfloat16_as_ushort(h0);
    }
#pragma unroll
    for (int o = 16; o; o >>= 1) sacc += __shfl_down_sync(0xffffffffu, sacc, o);
    if (lane == 0) s8[w] = sacc;
    __syncthreads();
    if (threadIdx.x < 4)
        g_cninit[lvl * (KCODES / 2) + blockIdx.x * 4 + threadIdx.x] =
            make_float2(-0.5f * s8[2 * threadIdx.x], -0.5f * s8[2 * threadIdx.x + 1]);
}

// ---------------- kernel: transpose codebook to [d][c] (refine uses it) ----------------
__global__ __launch_bounds__(256)
void btrans_kernel(const float* __restrict__ cb_top, const float* __restrict__ cb_bot) {
    __shared__ float s[32][33];
    int lvl = blockIdx.z;
    const float* cb = lvl ? cb_bot : cb_top;
    int c0 = blockIdx.x * 32, d0 = blockIdx.y * 32;
    int lx = threadIdx.x & 31, ly = threadIdx.x >> 5;
#pragma unroll
    for (int k = 0; k < 4; k++)
        s[ly + 8 * k][lx] = cb[(size_t)(c0 + ly + 8 * k) * DIM + d0 + lx];
    __syncthreads();
#pragma unroll
    for (int k = 0; k < 4; k++)
        g_bt[((size_t)lvl * DIM + d0 + ly + 8 * k) * KCODES + c0 + lx] = s[lx][ly + 8 * k];
}

// ---------------- argmin GEMM: x.e_hi on tensor pipe (2 GEMMs), persistent CTAs ----------------
// smem: A_hi 32KB | A_lo 32KB | B ring 4 x 4KB (e_hi only, 32B rows, XOR swizzle) => 80KB/CTA
#define SM_AHI 0
#define SM_ALO 32768
#define SM_B   65536
#define SM_RED 65536             // reduce scratch reuses B ring after mainloop
#define ARG_SMEM (65536 + 4 * 4096)

__device__ __forceinline__ void issueB(char* smem, int s, int tid, size_t L) {
    int nt = s >> 4, ch = s & 15, buf = s & 3;
    int row = tid >> 1, sg = tid & 1;
    char* bb = smem + SM_B + buf * 4096;
    size_t src = (L + nt * 128 + row) * (size_t)128 + ch * 8 + sg * 4;
    cp16(bb + row * 32 + ((sg ^ ((row >> 2) & 1)) << 4), &g_ehi[src]);
    CP_COMMIT();
}

__global__ __launch_bounds__(256, 2)
void argmin_kernel() {
    extern __shared__ __align__(128) char smem[];
    __shared__ int s_pos;
    int tid = threadIdx.x, lane = tid & 31, wid = tid >> 5;
    int wm = wid >> 2, wn = wid & 3;           // 2 warp-rows (32M) x 4 warp-cols (32N)
    uint32_t sb = (uint32_t)__cvta_generic_to_shared(smem);

    for (;;) {
        if (tid == 0) s_pos = atomicAdd(&g_tile_ctr, 1);
        __syncthreads();
        int pos = s_pos;
        if (pos >= NTILES) break;
        int lvl = pos >> 9;
        int m0 = (pos & 511) * 64;
        size_t XL = (size_t)lvl * NPTS;
        size_t EL = (size_t)lvl * KCODES;

#pragma unroll
        for (int i = 0; i < 8; i++) {
            int idx = tid + i * 256;
            int row = idx >> 5, seg = idx & 31;
            int soff = ((seg ^ (row & 7)) << 4);
            size_t src = (XL + m0 + row) * (size_t)128 + seg * 4;
            cp16(smem + SM_AHI + row * 512 + soff, &g_xhi[src]);
            cp16(smem + SM_ALO + row * 512 + soff, &g_xlo[src]);
        }
        CP_COMMIT();
        issueB(smem, 0, tid, EL);
        issueB(smem, 1, tid, EL);
        issueB(smem, 2, tid, EL);

        float tb[4], t2[4];
        int   ti[4];
#pragma unroll
        for (int r = 0; r < 4; r++) { tb[r] = -FLT_MAX; t2[r] = -FLT_MAX; ti[r] = 0; }

#pragma unroll 1
        for (int nt = 0; nt < 8; nt++) {
            float acc[2][4][4];
#pragma unroll
            for (int j = 0; j < 4; j++) {
                int c0 = nt * 128 + wn * 32 + j * 8 + (lane & 3) * 2;
                float2 ci = g_cninit[lvl * (KCODES / 2) + (c0 >> 1)];
#pragma unroll
                for (int mi = 0; mi < 2; mi++) {
                    acc[mi][j][0] = ci.x; acc[mi][j][1] = ci.y;
                    acc[mi][j][2] = ci.x; acc[mi][j][3] = ci.y;
                }
            }

#pragma unroll 1
            for (int ch = 0; ch < 16; ch++) {
                int s = nt * 16 + ch;
                if (s < 125) CP_WAIT2();
                else         CP_WAIT0();
                __syncthreads();
                if (s < 125) issueB(smem, s + 3, tid, EL);
                uint32_t bb = sb + SM_B + (s & 3) * 4096;

                uint32_t ah[2][4], al[2][4];
#pragma unroll
                for (int mi = 0; mi < 2; mi++) {
                    int p = wm * 32 + mi * 16 + (lane & 7) + ((lane >> 3) & 1) * 8;
                    int seg = ch * 2 + (lane >> 4);
                    uint32_t off = p * 512 + ((seg ^ (p & 7)) << 4);
                    lda4(ah[mi], sb + SM_AHI + off);
                    lda4(al[mi], sb + SM_ALO + off);
                }

                uint32_t bh[8];
                {
                    int g = lane >> 3, i = lane & 7;
                    int row0 = wn * 32 + (g >> 1) * 8 + i;
                    int row1 = row0 + 16;
                    uint32_t a0 = bb + row0 * 32 + (((g & 1) ^ ((row0 >> 2) & 1)) << 4);
                    uint32_t a1 = bb + row1 * 32 + (((g & 1) ^ ((row1 >> 2) & 1)) << 4);
                    lda4(&bh[0], a0);
                    lda4(&bh[4], a1);
                }
#pragma unroll
                for (int j = 0; j < 4; j++) {
#pragma unroll
                    for (int mi = 0; mi < 2; mi++) {
                        mma16816(acc[mi][j], ah[mi], &bh[2 * j]);
                        mma16816(acc[mi][j], al[mi], &bh[2 * j]);
                    }
                }
            }

#pragma unroll
            for (int j = 0; j < 4; j++) {
                int cbase = nt * 128 + wn * 32 + j * 8 + (lane & 3) * 2;
#pragma unroll
                for (int mi = 0; mi < 2; mi++)
#pragma unroll
                    for (int rh = 0; rh < 2; rh++) {
                        int r = mi * 2 + rh;
#pragma unroll
                        for (int cc = 0; cc < 2; cc++) {
                            float v = acc[mi][j][rh * 2 + cc];
                            int c = cbase + cc;
                            if (v > tb[r]) { t2[r] = tb[r]; tb[r] = v; ti[r] = c; }
                            else if (v > t2[r]) t2[r] = v;
                        }
                    }
            }
        }

#pragma unroll
        for (int k = 1; k <= 2; k <<= 1) {
#pragma unroll
            for (int r = 0; r < 4; r++) {
                float ob = __shfl_xor_sync(0xffffffffu, tb[r], k);
                float o2 = __shfl_xor_sync(0xffffffffu, t2[r], k);
                int   oi = __shfl_xor_sync(0xffffffffu, ti[r], k);
                if (ob > tb[r] || (ob == tb[r] && oi < ti[r])) {
                    t2[r] = fmaxf(tb[r], o2); tb[r] = ob; ti[r] = oi;
                } else {
                    t2[r] = fmaxf(t2[r], ob);
                }
            }
        }

        __syncthreads();
        float* rv  = (float*)(smem + SM_RED);
        float* r2v = rv + 256;
        int*   rix = (int*)(r2v + 256);
        if ((lane & 3) == 0) {
#pragma unroll
            for (int r = 0; r < 4; r++) {
                int row = wm * 32 + (r >> 1) * 16 + (r & 1) * 8 + (lane >> 2);
                rv[row * 4 + wn]  = tb[r];
                r2v[row * 4 + wn] = t2[r];
                rix[row * 4 + wn] = ti[r];
            }
        }
        __syncthreads();
        if (tid < 64) {
            float bv = rv[tid * 4];
            float bs = r2v[tid * 4];
            int   bi = rix[tid * 4];
#pragma unroll
            for (int x = 1; x < 4; x++) {
                float v  = rv[tid * 4 + x];
                float v2 = r2v[tid * 4 + x];
                int   ii = rix[tid * 4 + x];
                if (v > bv || (v == bv && ii < bi)) { bs = fmaxf(bv, v2); bv = v; bi = ii; }
                else                                 bs = fmaxf(bs, v);
            }
            g_idx[lvl][m0 + tid] = bi;
            if (bv - bs < TAU_S) {
                int p2 = atomicAdd(&g_refine_count[lvl], 1);
                g_refine_list[lvl][p2] = m0 + tid;
            }
        }
    }
}

// ---------------- kernel: batched two-stage refinement (parallel warp reductions) ----------------
__global__ __launch_bounds__(1024)
void refine_kernel(const float* __restrict__ h_top, const float* __restrict__ h_bot) {
    int lvl = blockIdx.y;
    const float* h = lvl ? h_bot : h_top;
    const float* bt = g_bt + (size_t)lvl * DIM * KCODES;
    int cnt = g_refine_count[lvl];

    __shared__ __align__(16) float2 xs2[DIM][4];   // 8KB: 4 point-pairs
    __shared__ float sd[8][1024];                  // 32KB: stage-A distances per point
    __shared__ int   plist[8];
    __shared__ int   sBf[8];

    int tid = threadIdx.x, lane = tid & 31, wid = tid >> 5;
    int c = tid;

    for (int base = blockIdx.x * 8; base < cnt; base += gridDim.x * 8) {
        int nb = min(8, cnt - base);
        __syncthreads();                            // previous round smem done
        if (tid < 8) {
            plist[tid] = g_refine_list[lvl][base + min(tid, nb - 1)];
            sBf[tid] = 0;
        }
        __syncthreads();
        // stage xs (pairs of points packed into float2 lanes)
        {
            int g = tid >> 7, dd = (tid & 127) * 2;
            int p = plist[g];
            int b = p / TLEN, t = p % TLEN;
            float v0 = h[((size_t)b * DIM + dd) * TLEN + t];
            float v1 = h[((size_t)b * DIM + dd + 1) * TLEN + t];
            if (g & 1) { xs2[dd][g >> 1].y = v0; xs2[dd + 1][g >> 1].y = v1; }
            else       { xs2[dd][g >> 1].x = v0; xs2[dd + 1][g >> 1].x = v1; }
        }
        __syncthreads();

        // ---- stage A: packed f32 distances for all 8 points in one bt sweep ----
        unsigned long long dv[4] = {0ull, 0ull, 0ull, 0ull};
        unsigned long long negone = pk2(-1.0f);
#pragma unroll 4
        for (int d = 0; d < DIM; d++) {
            unsigned long long ev2 = pk2(bt[(size_t)d * KCODES + c]);
#pragma unroll
            for (int q = 0; q < 4; q++) {
                unsigned long long x2 = *(const unsigned long long*)&xs2[d][q];
                unsigned long long df = fma2o(ev2, negone, x2);   // x - e (exact)
                fma2acc(dv[q], df, df);
            }
        }
#pragma unroll
        for (int q = 0; q < 4; q++) {
            float lo, hi;
            unpk2(dv[q], lo, hi);
            sd[2 * q][c]     = lo;
            sd[2 * q + 1][c] = hi;
        }
        __syncthreads();

        // ---- parallel top-2: warp g reduces point g ----
        if (wid < 8 && wid < nb) {
            int g = wid;
            float b = FLT_MAX, s = FLT_MAX;
            int   bi = 0;
#pragma unroll 8
            for (int k = 0; k < 32; k++) {
                int c2 = k * 32 + lane;              // conflict-free, ascending per lane
                float v = sd[g][c2];
                if (v < b || (v == b && c2 < bi)) { s = b; b = v; bi = c2; }
                else if (v < s) s = v;
            }
#pragma unroll
            for (int o = 16; o; o >>= 1) {
                float ob = __shfl_down_sync(0xffffffffu, b, o);
                float os = __shfl_down_sync(0xffffffffu, s, o);
                int   oi = __shfl_down_sync(0xffffffffu, bi, o);
                if (ob < b || (ob == b && oi < bi)) { s = fminf(b, os); b = ob; bi = oi; }
                else                                 s = fminf(s, ob);
            }
            if (lane == 0) {
                if (s - b >= TAU_EXACT) g_idx[lvl][plist[g]] = bi;
                else                    sBf[g] = 1;
            }
        }
        __syncthreads();

        // ---- stage B: compensated double-f32 exact (rare, full block per point) ----
        float* rb = sd[0];
        float* rl = sd[1];
        int*   rix = (int*)sd[2];
        for (int g = 0; g < nb; g++) {
            if (!sBf[g]) continue;
            int half = g >> 1;
            float hi = 0.f, lo = 0.f;
#pragma unroll 8
            for (int d = 0; d < DIM; d++) {
                float ev = bt[(size_t)d * KCODES + c];
                float x  = (g & 1) ? xs2[d][half].y : xs2[d][half].x;
                float s  = x - ev;
                float bb = s - x;
                float err = (x - (s - bb)) + ((-ev) - bb);
                float pq = s * s;
                float pe = fmaf(s, s, -pq);
                float cross = fmaf(2.f * s, err, fmaf(err, err, pe));
                float t1  = hi + pq;
                float bb2 = t1 - hi;
                float e2  = (hi - (t1 - bb2)) + (pq - bb2);
                hi = t1;
                lo += e2 + cross;
            }
            float th = hi + lo;
            float tl = lo - (th - hi);

            rb[tid] = th; rl[tid] = tl; rix[tid] = c;
            __syncthreads();
#pragma unroll
            for (int s = 512; s; s >>= 1) {
                if (tid < s) {
                    float oh = rb[tid + s], ol = rl[tid + s];
                    int   oi = rix[tid + s];
                    float mh = rb[tid], ml = rl[tid];
                    int   mi = rix[tid];
                    if (oh < mh || (oh == mh && (ol < ml || (ol == ml && oi < mi)))) {
                        rb[tid] = oh; rl[tid] = ol; rix[tid] = oi;
                    }
                }
                __syncthreads();
            }
            if (tid == 0) g_idx[lvl][plist[g]] = rix[0];
            __syncthreads();
        }
    }
}

// ---------------- kernel: gather z_q + per-block loss partials ----------------
__global__ __launch_bounds__(256)
void gather_kernel(const float* __restrict__ h_top, const float* __restrict__ h_bot,
                   const float* __restrict__ cb_top, const float* __restrict__ cb_bot,
                   float* __restrict__ out) {
    int lvl = blockIdx.z;
    const float* h  = lvl ? h_bot  : h_top;
    const float* cb = lvl ? cb_bot : cb_top;
    float* z = out + (size_t)lvl * NELEM;

    int b = blockIdx.y;
    int t0 = blockIdx.x * 32;
    int tid = threadIdx.x;

    __shared__ int   sidx[32];
    __shared__ float sh[32 * 33];
    __shared__ float red[256];

    if (tid < 32) sidx[tid] = g_idx[lvl][b * TLEN + t0 + tid];
    __syncthreads();

    float lacc = 0.f;
    int j2 = tid >> 3, l8 = tid & 7;

    for (int dc = 0; dc < DIM; dc += 32) {
        float4 v = *(const float4*)(cb + (size_t)sidx[j2] * DIM + dc + l8 * 4);
        sh[(l8 * 4 + 0) * 33 + j2] = v.x;
        sh[(l8 * 4 + 1) * 33 + j2] = v.y;
        sh[(l8 * 4 + 2) * 33 + j2] = v.z;
        sh[(l8 * 4 + 3) * 33 + j2] = v.w;
        __syncthreads();
#pragma unroll
        for (int it = 0; it < 4; it++) {
            int i = tid + it * 256;
            int dl = i >> 5, j = i & 31;
            size_t off = ((size_t)b * DIM + dc + dl) * TLEN + t0 + j;
            float zz = sh[dl * 33 + j];
            z[off] = zz;
            float e = h[off] - zz;
            lacc = fmaf(e, e, lacc);
        }
        __syncthreads();
    }

    red[tid] = lacc;
    __syncthreads();
#pragma unroll
    for (int s = 128; s; s >>= 1) {
        if (tid < s) red[tid] += red[tid + s];
        __syncthreads();
    }
    if (tid == 0) g_partial[lvl][blockIdx.y * (TLEN / 32) + blockIdx.x] = red[0];
}

// ---------------- kernel: finalize scalars ----------------
__global__ __launch_bounds__(1024)
void finalize_kernel(float* __restrict__ out) {
    __shared__ int   hist[KCODES];
    __shared__ float red[1024];
    int tid = threadIdx.x;

    float sums[2];
#pragma unroll
    for (int lvl = 0; lvl < 2; lvl++) {
        red[tid] = g_partial[lvl][tid];
        __syncthreads();
        for (int s = 512; s; s >>= 1) {
            if (tid < s) red[tid] += red[tid + s];
            __syncthreads();
        }
        sums[lvl] = red[0];
        __syncthreads();
    }
    float loss = sums[0] * (1.f / (float)NELEM) + sums[1] * (1.f / (float)NELEM);

    float ppl[2];
#pragma unroll
    for (int lvl = 0; lvl < 2; lvl++) {
        hist[tid] = 0;
        __syncthreads();
#pragma unroll
        for (int i = 0; i < NPTS / 1024; i++)
            atomicAdd(&hist[g_idx[lvl][i * 1024 + tid]], 1);
        __syncthreads();
        float p = (float)hist[tid] * (1.f / (float)NPTS);
        red[tid] = p * logf(p + 1e-10f);
        __syncthreads();
        for (int s = 512; s; s >>= 1) {
            if (tid < s) red[tid] += red[tid + s];
            __syncthreads();
        }
        ppl[lvl] = expf(-red[0]);
        __syncthreads();
    }

    if (tid == 0) {
        size_t base = (size_t)2 * NELEM;
        out[base + 0] = loss;
        out[base + 1] = loss;
        out[base + 2] = ppl[0];
        out[base + 3] = ppl[1];
    }
}

// ---------------- launcher ----------------
extern "C" void kernel_launch(void* const* d_in, const int* in_sizes, int n_in,
                              void* d_out, int out_size) {
    const float* h_top  = (const float*)d_in[0];
    const float* h_bot  = (const float*)d_in[1];
    const float* cb_top = (const float*)d_in[2];
    const float* cb_bot = (const float*)d_in[3];
    float* out = (float*)d_out;

    cudaFuncSetAttribute(argmin_kernel,
                         cudaFuncAttributeMaxDynamicSharedMemorySize, ARG_SMEM);

    xsplit_kernel<<<dim3(TLEN / 32, DIM / 64, BATCH * LEVELS), 256>>>(h_top, h_bot);
    ecnorm_kernel<<<dim3(KCODES / 8, LEVELS), 256>>>(cb_top, cb_bot);
    btrans_kernel<<<dim3(KCODES / 32, DIM / 32, LEVELS), 256>>>(cb_top, cb_bot);
    argmin_kernel<<<296, 256, ARG_SMEM>>>();
    refine_kernel<<<dim3(256, LEVELS), 1024>>>(h_top, h_bot);
    gather_kernel<<<dim3(TLEN / 32, BATCH, LEVELS), 256>>>(h_top, h_bot, cb_top, cb_bot, out);
    finalize_kernel<<<1, 1024>>>(out);
}